// round 1
// baseline (speedup 1.0000x reference)
#include <cuda_runtime.h>

// Fused Swin window-attention, one CTA per window (4096 CTAs, 256 thr).
// All GEMMs via mma.sync.m16n8k8 tf32 (fp32 accumulate).
// Tokens N=49 padded to M=64; DIM=128, NH=4, HD=32.

#define THREADS 256
constexpr int NTOK = 49;
constexpr int MPAD = 64;
constexpr int DIMC = 128;
constexpr int NHD  = 4;
constexpr int HD   = 32;
constexpr int NWIN = 64;
constexpr float SCALE = 0.17677669529663687f; // 32^-0.5

// shared-memory float offsets (padded strides for conflict-free fragment loads)
constexpr int LDX  = 132;            // 128-col buffers
constexpr int LDS2 = 68;             // 64-col score buffer
constexpr int XS   = 0;              // x tile / later ctx tile  (64x132)
constexpr int QS   = XS + MPAD * LDX;
constexpr int KS   = QS + MPAD * LDX;
constexpr int VS   = KS + MPAD * LDX;
constexpr int WSO  = VS + MPAD * LDX;   // weight chunk 128x132
constexpr int SSO  = WSO;               // scores 64x68 (overlaps weight region)
constexpr int IDXO = WSO + 128 * LDX;   // 2401 ints
constexpr int TBLO = IDXO + 2404;       // 676 floats
constexpr int SMEM_FLOATS = TBLO + 680;

__device__ __forceinline__ unsigned f2tf(float x) {
    unsigned r;
    asm("cvt.rna.tf32.f32 %0, %1;" : "=r"(r) : "f"(x));
    return r;
}

__device__ __forceinline__ void mma8(float c[4],
                                     unsigned a0, unsigned a1, unsigned a2, unsigned a3,
                                     unsigned b0, unsigned b1) {
    asm volatile(
        "mma.sync.aligned.m16n8k8.row.col.f32.tf32.tf32.f32 "
        "{%0,%1,%2,%3},{%4,%5,%6,%7},{%8,%9},{%0,%1,%2,%3};"
        : "+f"(c[0]), "+f"(c[1]), "+f"(c[2]), "+f"(c[3])
        : "r"(a0), "r"(a1), "r"(a2), "r"(a3), "r"(b0), "r"(b1));
}

__device__ __forceinline__ unsigned ldsm(const float* p) { return __float_as_uint(*p); }

__global__ __launch_bounds__(THREADS, 1)
void swin_win_attn_kernel(const float* __restrict__ x,
                          const float* __restrict__ mask,
                          const float* __restrict__ qkv_w,
                          const float* __restrict__ qkv_b,
                          const float* __restrict__ proj_w,
                          const float* __restrict__ proj_b,
                          const float* __restrict__ tbl_g,
                          const int*   __restrict__ idx_g,
                          float* __restrict__ out) {
    extern __shared__ float sm[];
    int*   idx_s = (int*)(sm + IDXO);
    float* tbl_s = sm + TBLO;

    const int tid  = threadIdx.x;
    const int lane = tid & 31;
    const int w    = tid >> 5;
    const int b    = blockIdx.x;
    const int win  = b & (NWIN - 1);

    const int wm = w & 3;       // M-tile row (16 rows each)
    const int wn = w >> 2;      // N split
    const int ar = lane >> 2;   // fragment group id
    const int ac = lane & 3;    // fragment thread-in-group

    // ---- stage rel index + bias table ----
    for (int i = tid; i < NTOK * NTOK; i += THREADS) idx_s[i] = idx_g[i];
    for (int i = tid; i < 169 * NHD;   i += THREADS) tbl_s[i] = tbl_g[i];

    // ---- zero pad rows of x tile, then load x (tf32-rounded) ----
    for (int i = tid; i < (MPAD - NTOK) * DIMC; i += THREADS) {
        int r = NTOK + i / DIMC, c = i % DIMC;
        sm[XS + r * LDX + c] = 0.f;
    }
    {
        const float4* xg = (const float4*)(x + (size_t)b * NTOK * DIMC);
        for (int i = tid; i < NTOK * DIMC / 4; i += THREADS) {
            int r = i >> 5, c4 = i & 31;
            float4 v = __ldg(xg + i);
            float* d = sm + XS + r * LDX + c4 * 4;
            d[0] = __uint_as_float(f2tf(v.x));
            d[1] = __uint_as_float(f2tf(v.y));
            d[2] = __uint_as_float(f2tf(v.z));
            d[3] = __uint_as_float(f2tf(v.w));
        }
    }
    __syncthreads();

    // ================= QKV: 3 chunks of 128 output cols =================
    for (int ch = 0; ch < 3; ++ch) {
        const float4* wg = (const float4*)(qkv_w + ch * DIMC * DIMC);
        for (int i = tid; i < DIMC * DIMC / 4; i += THREADS) {
            int r = i >> 5, c4 = i & 31;
            float4 v = __ldg(wg + i);
            float* d = sm + WSO + r * LDX + c4 * 4;
            d[0] = __uint_as_float(f2tf(v.x));
            d[1] = __uint_as_float(f2tf(v.y));
            d[2] = __uint_as_float(f2tf(v.z));
            d[3] = __uint_as_float(f2tf(v.w));
        }
        __syncthreads();

        float acc[8][4];
        #pragma unroll
        for (int t = 0; t < 8; ++t)
            #pragma unroll
            for (int j = 0; j < 4; ++j) acc[t][j] = 0.f;

        #pragma unroll 4
        for (int k0 = 0; k0 < DIMC; k0 += 8) {
            const float* Xb = sm + XS + (wm * 16) * LDX + k0;
            unsigned a0 = ldsm(Xb + ar * LDX + ac);
            unsigned a1 = ldsm(Xb + (ar + 8) * LDX + ac);
            unsigned a2 = ldsm(Xb + ar * LDX + ac + 4);
            unsigned a3 = ldsm(Xb + (ar + 8) * LDX + ac + 4);
            #pragma unroll
            for (int t = 0; t < 8; ++t) {
                int n0 = wn * 64 + t * 8;
                unsigned b0 = ldsm(sm + WSO + (n0 + ar) * LDX + k0 + ac);
                unsigned b1 = ldsm(sm + WSO + (n0 + ar) * LDX + k0 + 4 + ac);
                mma8(acc[t], a0, a1, a2, a3, b0, b1);
            }
        }

        float* dst = sm + (ch == 0 ? QS : (ch == 1 ? KS : VS));
        float scl = (ch == 0) ? SCALE : 1.f;
        #pragma unroll
        for (int t = 0; t < 8; ++t) {
            int col = wn * 64 + t * 8 + 2 * ac;
            float b0v = __ldg(qkv_b + ch * DIMC + col);
            float b1v = __ldg(qkv_b + ch * DIMC + col + 1);
            int r0 = wm * 16 + ar;
            dst[r0 * LDX + col]           = __uint_as_float(f2tf((acc[t][0] + b0v) * scl));
            dst[r0 * LDX + col + 1]       = __uint_as_float(f2tf((acc[t][1] + b1v) * scl));
            dst[(r0 + 8) * LDX + col]     = __uint_as_float(f2tf((acc[t][2] + b0v) * scl));
            dst[(r0 + 8) * LDX + col + 1] = __uint_as_float(f2tf((acc[t][3] + b1v) * scl));
        }
        __syncthreads();
    }

    // ================= attention, per head =================
    const float* mask_g = mask + (size_t)win * NTOK * NTOK;
    for (int h = 0; h < NHD; ++h) {
        // --- scores S = Q_h @ K_h^T  (64x64, K=32) ---
        float sacc[4][4];
        #pragma unroll
        for (int t = 0; t < 4; ++t)
            #pragma unroll
            for (int j = 0; j < 4; ++j) sacc[t][j] = 0.f;

        #pragma unroll
        for (int kk = 0; kk < 4; ++kk) {
            int k0 = h * HD + kk * 8;
            const float* Qb = sm + QS + (wm * 16) * LDX + k0;
            unsigned a0 = ldsm(Qb + ar * LDX + ac);
            unsigned a1 = ldsm(Qb + (ar + 8) * LDX + ac);
            unsigned a2 = ldsm(Qb + ar * LDX + ac + 4);
            unsigned a3 = ldsm(Qb + (ar + 8) * LDX + ac + 4);
            #pragma unroll
            for (int t = 0; t < 4; ++t) {
                int m0 = wn * 32 + t * 8;
                unsigned b0 = ldsm(sm + KS + (m0 + ar) * LDX + k0 + ac);
                unsigned b1 = ldsm(sm + KS + (m0 + ar) * LDX + k0 + 4 + ac);
                mma8(sacc[t], a0, a1, a2, a3, b0, b1);
            }
        }
        #pragma unroll
        for (int t = 0; t < 4; ++t) {
            int m0 = wn * 32 + t * 8 + 2 * ac;
            int r0 = wm * 16 + ar;
            sm[SSO + r0 * LDS2 + m0]           = sacc[t][0];
            sm[SSO + r0 * LDS2 + m0 + 1]       = sacc[t][1];
            sm[SSO + (r0 + 8) * LDS2 + m0]     = sacc[t][2];
            sm[SSO + (r0 + 8) * LDS2 + m0 + 1] = sacc[t][3];
        }
        __syncthreads();

        // --- softmax with rel-bias + shift-mask (warp w owns rows w*8..w*8+7) ---
        for (int rr = 0; rr < 8; ++rr) {
            int n = w * 8 + rr;
            float s0 = -1e30f, s1 = -1e30f;
            if (n < NTOK) {
                if (lane < NTOK)
                    s0 = sm[SSO + n * LDS2 + lane]
                       + tbl_s[idx_s[n * NTOK + lane] * NHD + h]
                       + __ldg(mask_g + n * NTOK + lane);
                int m1 = lane + 32;
                if (m1 < NTOK)
                    s1 = sm[SSO + n * LDS2 + m1]
                       + tbl_s[idx_s[n * NTOK + m1] * NHD + h]
                       + __ldg(mask_g + n * NTOK + m1);
            }
            float mx = fmaxf(s0, s1);
            #pragma unroll
            for (int o = 16; o; o >>= 1) mx = fmaxf(mx, __shfl_xor_sync(0xffffffffu, mx, o));
            float e0 = (s0 > -1e29f) ? __expf(s0 - mx) : 0.f;
            float e1 = (s1 > -1e29f) ? __expf(s1 - mx) : 0.f;
            float sum = e0 + e1;
            #pragma unroll
            for (int o = 16; o; o >>= 1) sum += __shfl_xor_sync(0xffffffffu, sum, o);
            if (n < NTOK) {
                float inv = 1.f / sum;
                sm[SSO + n * LDS2 + lane]      = __uint_as_float(f2tf(e0 * inv));
                sm[SSO + n * LDS2 + lane + 32] = __uint_as_float(f2tf(e1 * inv));
            } else {
                sm[SSO + n * LDS2 + lane]      = 0.f;
                sm[SSO + n * LDS2 + lane + 32] = 0.f;
            }
        }
        __syncthreads();

        // --- ctx_h = P @ V_h  (64x32, K=64) ---
        float cacc[2][4];
        #pragma unroll
        for (int u = 0; u < 2; ++u)
            #pragma unroll
            for (int j = 0; j < 4; ++j) cacc[u][j] = 0.f;

        #pragma unroll
        for (int k0 = 0; k0 < MPAD; k0 += 8) {
            const float* Pb = sm + SSO + (wm * 16) * LDS2 + k0;
            unsigned a0 = ldsm(Pb + ar * LDS2 + ac);
            unsigned a1 = ldsm(Pb + (ar + 8) * LDS2 + ac);
            unsigned a2 = ldsm(Pb + ar * LDS2 + ac + 4);
            unsigned a3 = ldsm(Pb + (ar + 8) * LDS2 + ac + 4);
            #pragma unroll
            for (int u = 0; u < 2; ++u) {
                int n0 = h * HD + wn * 16 + u * 8;
                unsigned b0 = ldsm(sm + VS + (k0 + ac) * LDX + n0 + ar);
                unsigned b1 = ldsm(sm + VS + (k0 + 4 + ac) * LDX + n0 + ar);
                mma8(cacc[u], a0, a1, a2, a3, b0, b1);
            }
        }
        #pragma unroll
        for (int u = 0; u < 2; ++u) {
            int col = h * HD + wn * 16 + u * 8 + 2 * ac;
            int r0 = wm * 16 + ar;
            sm[XS + r0 * LDX + col]           = __uint_as_float(f2tf(cacc[u][0]));
            sm[XS + r0 * LDX + col + 1]       = __uint_as_float(f2tf(cacc[u][1]));
            sm[XS + (r0 + 8) * LDX + col]     = __uint_as_float(f2tf(cacc[u][2]));
            sm[XS + (r0 + 8) * LDX + col + 1] = __uint_as_float(f2tf(cacc[u][3]));
        }
        __syncthreads();
    }

    // ================= proj: out = ctx @ proj_w^T + proj_b =================
    {
        const float4* pg = (const float4*)proj_w;
        for (int i = tid; i < DIMC * DIMC / 4; i += THREADS) {
            int r = i >> 5, c4 = i & 31;
            float4 v = __ldg(pg + i);
            float* d = sm + WSO + r * LDX + c4 * 4;
            d[0] = __uint_as_float(f2tf(v.x));
            d[1] = __uint_as_float(f2tf(v.y));
            d[2] = __uint_as_float(f2tf(v.z));
            d[3] = __uint_as_float(f2tf(v.w));
        }
        __syncthreads();

        float pacc[8][4];
        #pragma unroll
        for (int t = 0; t < 8; ++t)
            #pragma unroll
            for (int j = 0; j < 4; ++j) pacc[t][j] = 0.f;

        #pragma unroll 4
        for (int k0 = 0; k0 < DIMC; k0 += 8) {
            const float* Cb = sm + XS + (wm * 16) * LDX + k0;
            unsigned a0 = ldsm(Cb + ar * LDX + ac);
            unsigned a1 = ldsm(Cb + (ar + 8) * LDX + ac);
            unsigned a2 = ldsm(Cb + ar * LDX + ac + 4);
            unsigned a3 = ldsm(Cb + (ar + 8) * LDX + ac + 4);
            #pragma unroll
            for (int t = 0; t < 8; ++t) {
                int n0 = wn * 64 + t * 8;
                unsigned b0 = ldsm(sm + WSO + (n0 + ar) * LDX + k0 + ac);
                unsigned b1 = ldsm(sm + WSO + (n0 + ar) * LDX + k0 + 4 + ac);
                mma8(pacc[t], a0, a1, a2, a3, b0, b1);
            }
        }

        float* og = out + (size_t)b * NTOK * DIMC;
        #pragma unroll
        for (int t = 0; t < 8; ++t) {
            int col = wn * 64 + t * 8 + 2 * ac;
            float b0v = __ldg(proj_b + col);
            float b1v = __ldg(proj_b + col + 1);
            int r0 = wm * 16 + ar;
            if (r0 < NTOK) {
                og[r0 * DIMC + col]     = pacc[t][0] + b0v;
                og[r0 * DIMC + col + 1] = pacc[t][1] + b1v;
            }
            if (r0 + 8 < NTOK) {
                og[(r0 + 8) * DIMC + col]     = pacc[t][2] + b0v;
                og[(r0 + 8) * DIMC + col + 1] = pacc[t][3] + b1v;
            }
        }
    }
}

extern "C" void kernel_launch(void* const* d_in, const int* in_sizes, int n_in,
                              void* d_out, int out_size) {
    const float* x      = (const float*)d_in[0];
    const float* mask   = (const float*)d_in[1];
    const float* qkv_w  = (const float*)d_in[2];
    const float* qkv_b  = (const float*)d_in[3];
    const float* proj_w = (const float*)d_in[4];
    const float* proj_b = (const float*)d_in[5];
    const float* tbl    = (const float*)d_in[6];
    const int*   idx    = (const int*)d_in[7];

    cudaFuncSetAttribute(swin_win_attn_kernel,
                         cudaFuncAttributeMaxDynamicSharedMemorySize,
                         SMEM_FLOATS * 4);

    swin_win_attn_kernel<<<4096, THREADS, SMEM_FLOATS * 4>>>(
        x, mask, qkv_w, qkv_b, proj_w, proj_b, tbl, idx, (float*)d_out);
}

// round 2
// speedup vs baseline: 1.3611x; 1.3611x over previous
#include <cuda_runtime.h>

// Fused Swin window-attention, one CTA per window (4096 CTAs, 512 thr / 16 warps).
// All GEMMs via mma.sync.m16n8k8 tf32 (fp32 accumulate), fragments via ldmatrix.
// Tokens N=49 padded to M=64; DIM=128, NH=4, HD=32.

#define THREADS 512
constexpr int NTOK = 49;
constexpr int MPAD = 64;
constexpr int DIMC = 128;
constexpr int NHD  = 4;
constexpr int HD   = 32;
constexpr int NWIN = 64;
constexpr float SCALE = 0.17677669529663687f; // 32^-0.5

// shared-memory float offsets (stride 132 / 68 -> rows shift 4 banks, conflict-free ldmatrix)
constexpr int LDX  = 132;
constexpr int LDS2 = 68;
constexpr int XS   = 0;                 // x tile, later ctx tile (64x132)
constexpr int QS   = XS + MPAD * LDX;
constexpr int KS   = QS + MPAD * LDX;
constexpr int VS   = KS + MPAD * LDX;
constexpr int WSO  = VS + MPAD * LDX;   // weight chunk 128x132
constexpr int SSO  = WSO;               // scores 64x68 (overlaps weight region)
constexpr int IDXO = WSO + 128 * LDX;   // 2401 ints
constexpr int TBLO = IDXO + 2404;       // 676 floats
constexpr int SMEM_FLOATS = TBLO + 680;

__device__ __forceinline__ unsigned f2tf(float x) {
    unsigned r;
    asm("cvt.rna.tf32.f32 %0, %1;" : "=r"(r) : "f"(x));
    return r;
}

__device__ __forceinline__ void mma8(float c[4],
                                     unsigned a0, unsigned a1, unsigned a2, unsigned a3,
                                     unsigned b0, unsigned b1) {
    asm volatile(
        "mma.sync.aligned.m16n8k8.row.col.f32.tf32.tf32.f32 "
        "{%0,%1,%2,%3},{%4,%5,%6,%7},{%8,%9},{%0,%1,%2,%3};"
        : "+f"(c[0]), "+f"(c[1]), "+f"(c[2]), "+f"(c[3])
        : "r"(a0), "r"(a1), "r"(a2), "r"(a3), "r"(b0), "r"(b1));
}

__device__ __forceinline__ unsigned sptr(const float* p) {
    return (unsigned)__cvta_generic_to_shared(p);
}

// A fragment (16x8 tf32 tile at base, row stride L): a0..a3 via ldmatrix.x4
__device__ __forceinline__ void ldA(unsigned r[4], const float* base, int L) {
    int lane = threadIdx.x & 31;
    int tr = lane & 7;
    const float* p = base + (tr + ((lane & 8) ? 8 : 0)) * L + ((lane & 16) ? 4 : 0);
    unsigned a = sptr(p);
    asm volatile("ldmatrix.sync.aligned.m8n8.x4.shared.b16 {%0,%1,%2,%3}, [%4];"
                 : "=r"(r[0]), "=r"(r[1]), "=r"(r[2]), "=r"(r[3]) : "r"(a));
}

// B fragment (8(n) x 8(k) tf32 tile, rows indexed by n at base, stride L): b0,b1 via ldmatrix.x2
__device__ __forceinline__ void ldB(unsigned r[2], const float* base, int L) {
    int lane = threadIdx.x & 31;
    int tr = lane & 7;
    const float* p = base + tr * L + ((lane & 8) ? 4 : 0);
    unsigned a = sptr(p);
    asm volatile("ldmatrix.sync.aligned.m8n8.x2.shared.b16 {%0,%1}, [%2];"
                 : "=r"(r[0]), "=r"(r[1]) : "r"(a));
}

__device__ __forceinline__ unsigned ldsm(const float* p) { return __float_as_uint(*p); }

__global__ __launch_bounds__(THREADS, 1)
void swin_win_attn_kernel(const float* __restrict__ x,
                          const float* __restrict__ mask,
                          const float* __restrict__ qkv_w,
                          const float* __restrict__ qkv_b,
                          const float* __restrict__ proj_w,
                          const float* __restrict__ proj_b,
                          const float* __restrict__ tbl_g,
                          const int*   __restrict__ idx_g,
                          float* __restrict__ out) {
    extern __shared__ float sm[];
    int*   idx_s = (int*)(sm + IDXO);
    float* tbl_s = sm + TBLO;

    const int tid  = threadIdx.x;
    const int lane = tid & 31;
    const int w    = tid >> 5;
    const int b    = blockIdx.x;
    const int win  = b & (NWIN - 1);

    const int wm = w & 3;       // M-tile (16 rows)
    const int wn = w >> 2;      // N-tile (0..3)
    const int ar = lane >> 2;
    const int ac = lane & 3;

    // ---- stage rel index + bias table ----
    for (int i = tid; i < NTOK * NTOK; i += THREADS) idx_s[i] = idx_g[i];
    for (int i = tid; i < 169 * NHD;   i += THREADS) tbl_s[i] = tbl_g[i];

    // ---- zero pad rows of x tile, then load x (tf32-rounded) ----
    for (int i = tid; i < (MPAD - NTOK) * DIMC; i += THREADS) {
        int r = NTOK + i / DIMC, c = i % DIMC;
        sm[XS + r * LDX + c] = 0.f;
    }
    {
        const float4* xg = (const float4*)(x + (size_t)b * NTOK * DIMC);
        for (int i = tid; i < NTOK * DIMC / 4; i += THREADS) {
            int r = i >> 5, c4 = i & 31;
            float4 v = __ldg(xg + i);
            float* d = sm + XS + r * LDX + c4 * 4;
            d[0] = __uint_as_float(f2tf(v.x));
            d[1] = __uint_as_float(f2tf(v.y));
            d[2] = __uint_as_float(f2tf(v.z));
            d[3] = __uint_as_float(f2tf(v.w));
        }
    }
    __syncthreads();

    // ================= QKV: 3 chunks of 128 output cols =================
    for (int ch = 0; ch < 3; ++ch) {
        const float4* wg = (const float4*)(qkv_w + ch * DIMC * DIMC);
        for (int i = tid; i < DIMC * DIMC / 4; i += THREADS) {
            int r = i >> 5, c4 = i & 31;
            float4 v = __ldg(wg + i);
            float* d = sm + WSO + r * LDX + c4 * 4;
            d[0] = __uint_as_float(f2tf(v.x));
            d[1] = __uint_as_float(f2tf(v.y));
            d[2] = __uint_as_float(f2tf(v.z));
            d[3] = __uint_as_float(f2tf(v.w));
        }
        __syncthreads();

        float acc[4][4];
        #pragma unroll
        for (int t = 0; t < 4; ++t)
            #pragma unroll
            for (int j = 0; j < 4; ++j) acc[t][j] = 0.f;

        #pragma unroll 4
        for (int k0 = 0; k0 < DIMC; k0 += 8) {
            unsigned a[4];
            ldA(a, sm + XS + (wm * 16) * LDX + k0, LDX);
            #pragma unroll
            for (int t = 0; t < 4; ++t) {
                int n0 = wn * 32 + t * 8;
                unsigned bb[2];
                ldB(bb, sm + WSO + n0 * LDX + k0, LDX);
                mma8(acc[t], a[0], a[1], a[2], a[3], bb[0], bb[1]);
            }
        }

        float* dst = sm + (ch == 0 ? QS : (ch == 1 ? KS : VS));
        float scl = (ch == 0) ? SCALE : 1.f;
        #pragma unroll
        for (int t = 0; t < 4; ++t) {
            int col = wn * 32 + t * 8 + 2 * ac;
            float b0v = __ldg(qkv_b + ch * DIMC + col);
            float b1v = __ldg(qkv_b + ch * DIMC + col + 1);
            int r0 = wm * 16 + ar;
            dst[r0 * LDX + col]           = __uint_as_float(f2tf((acc[t][0] + b0v) * scl));
            dst[r0 * LDX + col + 1]       = __uint_as_float(f2tf((acc[t][1] + b1v) * scl));
            dst[(r0 + 8) * LDX + col]     = __uint_as_float(f2tf((acc[t][2] + b0v) * scl));
            dst[(r0 + 8) * LDX + col + 1] = __uint_as_float(f2tf((acc[t][3] + b1v) * scl));
        }
        __syncthreads();
    }

    // ================= attention, per head =================
    const float* mask_g = mask + (size_t)win * NTOK * NTOK;
    for (int h = 0; h < NHD; ++h) {
        // --- scores S = Q_h @ K_h^T  (64x64, K=32) ---
        float sacc[2][4];
        #pragma unroll
        for (int t = 0; t < 2; ++t)
            #pragma unroll
            for (int j = 0; j < 4; ++j) sacc[t][j] = 0.f;

        #pragma unroll
        for (int kk = 0; kk < 4; ++kk) {
            int k0 = h * HD + kk * 8;
            unsigned a[4];
            ldA(a, sm + QS + (wm * 16) * LDX + k0, LDX);
            #pragma unroll
            for (int t = 0; t < 2; ++t) {
                int m0 = wn * 16 + t * 8;
                unsigned bb[2];
                ldB(bb, sm + KS + m0 * LDX + k0, LDX);
                mma8(sacc[t], a[0], a[1], a[2], a[3], bb[0], bb[1]);
            }
        }
        #pragma unroll
        for (int t = 0; t < 2; ++t) {
            int m0 = wn * 16 + t * 8 + 2 * ac;
            int r0 = wm * 16 + ar;
            sm[SSO + r0 * LDS2 + m0]           = sacc[t][0];
            sm[SSO + r0 * LDS2 + m0 + 1]       = sacc[t][1];
            sm[SSO + (r0 + 8) * LDS2 + m0]     = sacc[t][2];
            sm[SSO + (r0 + 8) * LDS2 + m0 + 1] = sacc[t][3];
        }
        __syncthreads();

        // --- softmax with rel-bias + shift-mask (warp w owns rows w*4..w*4+3) ---
        #pragma unroll
        for (int rr = 0; rr < 4; ++rr) {
            int n = w * 4 + rr;
            float s0 = -1e30f, s1 = -1e30f;
            if (n < NTOK) {
                if (lane < NTOK)
                    s0 = sm[SSO + n * LDS2 + lane]
                       + tbl_s[idx_s[n * NTOK + lane] * NHD + h]
                       + __ldg(mask_g + n * NTOK + lane);
                int m1 = lane + 32;
                if (m1 < NTOK)
                    s1 = sm[SSO + n * LDS2 + m1]
                       + tbl_s[idx_s[n * NTOK + m1] * NHD + h]
                       + __ldg(mask_g + n * NTOK + m1);
            }
            float mx = fmaxf(s0, s1);
            #pragma unroll
            for (int o = 16; o; o >>= 1) mx = fmaxf(mx, __shfl_xor_sync(0xffffffffu, mx, o));
            float e0 = (s0 > -1e29f) ? __expf(s0 - mx) : 0.f;
            float e1 = (s1 > -1e29f) ? __expf(s1 - mx) : 0.f;
            float sum = e0 + e1;
            #pragma unroll
            for (int o = 16; o; o >>= 1) sum += __shfl_xor_sync(0xffffffffu, sum, o);
            if (n < NTOK) {
                float inv = 1.f / sum;
                sm[SSO + n * LDS2 + lane]      = __uint_as_float(f2tf(e0 * inv));
                sm[SSO + n * LDS2 + lane + 32] = __uint_as_float(f2tf(e1 * inv));
            } else {
                sm[SSO + n * LDS2 + lane]      = 0.f;
                sm[SSO + n * LDS2 + lane + 32] = 0.f;
            }
        }
        __syncthreads();

        // --- ctx_h = P @ V_h  (64x32, K=64); warp tile 16x8 ---
        float cacc[4];
        #pragma unroll
        for (int j = 0; j < 4; ++j) cacc[j] = 0.f;

        int n0 = h * HD + wn * 8;
        #pragma unroll
        for (int k0 = 0; k0 < MPAD; k0 += 8) {
            unsigned a[4];
            ldA(a, sm + SSO + (wm * 16) * LDS2 + k0, LDS2);
            unsigned b0 = ldsm(sm + VS + (k0 + ac) * LDX + n0 + ar);
            unsigned b1 = ldsm(sm + VS + (k0 + 4 + ac) * LDX + n0 + ar);
            mma8(cacc, a[0], a[1], a[2], a[3], b0, b1);
        }
        {
            int col = n0 + 2 * ac;
            int r0 = wm * 16 + ar;
            sm[XS + r0 * LDX + col]           = __uint_as_float(f2tf(cacc[0]));
            sm[XS + r0 * LDX + col + 1]       = __uint_as_float(f2tf(cacc[1]));
            sm[XS + (r0 + 8) * LDX + col]     = __uint_as_float(f2tf(cacc[2]));
            sm[XS + (r0 + 8) * LDX + col + 1] = __uint_as_float(f2tf(cacc[3]));
        }
        __syncthreads();
    }

    // ================= proj: out = ctx @ proj_w^T + proj_b =================
    {
        const float4* pg = (const float4*)proj_w;
        for (int i = tid; i < DIMC * DIMC / 4; i += THREADS) {
            int r = i >> 5, c4 = i & 31;
            float4 v = __ldg(pg + i);
            float* d = sm + WSO + r * LDX + c4 * 4;
            d[0] = __uint_as_float(f2tf(v.x));
            d[1] = __uint_as_float(f2tf(v.y));
            d[2] = __uint_as_float(f2tf(v.z));
            d[3] = __uint_as_float(f2tf(v.w));
        }
        __syncthreads();

        float pacc[4][4];
        #pragma unroll
        for (int t = 0; t < 4; ++t)
            #pragma unroll
            for (int j = 0; j < 4; ++j) pacc[t][j] = 0.f;

        #pragma unroll 4
        for (int k0 = 0; k0 < DIMC; k0 += 8) {
            unsigned a[4];
            ldA(a, sm + XS + (wm * 16) * LDX + k0, LDX);
            #pragma unroll
            for (int t = 0; t < 4; ++t) {
                int n0 = wn * 32 + t * 8;
                unsigned bb[2];
                ldB(bb, sm + WSO + n0 * LDX + k0, LDX);
                mma8(pacc[t], a[0], a[1], a[2], a[3], bb[0], bb[1]);
            }
        }

        float* og = out + (size_t)b * NTOK * DIMC;
        #pragma unroll
        for (int t = 0; t < 4; ++t) {
            int col = wn * 32 + t * 8 + 2 * ac;
            float b0v = __ldg(proj_b + col);
            float b1v = __ldg(proj_b + col + 1);
            int r0 = wm * 16 + ar;
            if (r0 < NTOK) {
                og[r0 * DIMC + col]     = pacc[t][0] + b0v;
                og[r0 * DIMC + col + 1] = pacc[t][1] + b1v;
            }
            if (r0 + 8 < NTOK) {
                og[(r0 + 8) * DIMC + col]     = pacc[t][2] + b0v;
                og[(r0 + 8) * DIMC + col + 1] = pacc[t][3] + b1v;
            }
        }
    }
}

extern "C" void kernel_launch(void* const* d_in, const int* in_sizes, int n_in,
                              void* d_out, int out_size) {
    const float* x      = (const float*)d_in[0];
    const float* mask   = (const float*)d_in[1];
    const float* qkv_w  = (const float*)d_in[2];
    const float* qkv_b  = (const float*)d_in[3];
    const float* proj_w = (const float*)d_in[4];
    const float* proj_b = (const float*)d_in[5];
    const float* tbl    = (const float*)d_in[6];
    const int*   idx    = (const int*)d_in[7];

    cudaFuncSetAttribute(swin_win_attn_kernel,
                         cudaFuncAttributeMaxDynamicSharedMemorySize,
                         SMEM_FLOATS * 4);

    swin_win_attn_kernel<<<4096, THREADS, SMEM_FLOATS * 4>>>(
        x, mask, qkv_w, qkv_b, proj_w, proj_b, tbl, idx, (float*)d_out);
}

// round 3
// speedup vs baseline: 1.3942x; 1.0243x over previous
#include <cuda_runtime.h>

// Fused Swin window-attention, one CTA per window (4096 CTAs, 512 thr / 16 warps).
// GEMMs via mma.sync.m16n8k8 tf32, fragments via ldmatrix. Heads processed in parallel.

#define THREADS 512
constexpr int NTOK = 49;
constexpr int MPAD = 64;
constexpr int DIMC = 128;
constexpr int NHD  = 4;
constexpr int HD   = 32;
constexpr int NWIN = 64;
constexpr float SCALE = 0.17677669529663687f; // 32^-0.5

constexpr int LDX  = 132;
constexpr int LDS2 = 68;
constexpr int SBUF = MPAD * LDS2;          // 4352 per-head score buffer
constexpr int XS   = 0;                    // x tile / ctx tile (64x132)
constexpr int QS   = XS + MPAD * LDX;
constexpr int KS   = QS + MPAD * LDX;
constexpr int VS   = KS + MPAD * LDX;
constexpr int WSO  = VS + MPAD * LDX;      // weight chunk 128x132 (16896)
constexpr int SSO  = WSO;                  // 4 score buffers (17408), overlap weights
constexpr int WREG = 4 * SBUF;             // 17408 > 16896
constexpr int IDXO = WSO + WREG;           // 2401 ints
constexpr int MSKO = IDXO + 2404;          // 2401 floats
constexpr int TBLO = MSKO + 2404;          // 676 floats
constexpr int SMEM_FLOATS = TBLO + 680;    // ~226.8 KB

__device__ __forceinline__ unsigned f2tf(float x) {
    unsigned r;
    asm("cvt.rna.tf32.f32 %0, %1;" : "=r"(r) : "f"(x));
    return r;
}
__device__ __forceinline__ float4 f2tf4(float4 v) {
    float4 t;
    t.x = __uint_as_float(f2tf(v.x));
    t.y = __uint_as_float(f2tf(v.y));
    t.z = __uint_as_float(f2tf(v.z));
    t.w = __uint_as_float(f2tf(v.w));
    return t;
}

__device__ __forceinline__ void mma8(float c[4],
                                     unsigned a0, unsigned a1, unsigned a2, unsigned a3,
                                     unsigned b0, unsigned b1) {
    asm volatile(
        "mma.sync.aligned.m16n8k8.row.col.f32.tf32.tf32.f32 "
        "{%0,%1,%2,%3},{%4,%5,%6,%7},{%8,%9},{%0,%1,%2,%3};"
        : "+f"(c[0]), "+f"(c[1]), "+f"(c[2]), "+f"(c[3])
        : "r"(a0), "r"(a1), "r"(a2), "r"(a3), "r"(b0), "r"(b1));
}

__device__ __forceinline__ unsigned sptr(const float* p) {
    return (unsigned)__cvta_generic_to_shared(p);
}

__device__ __forceinline__ void ldA(unsigned r[4], const float* base, int L) {
    int lane = threadIdx.x & 31;
    const float* p = base + ((lane & 7) + ((lane & 8) ? 8 : 0)) * L + ((lane & 16) ? 4 : 0);
    unsigned a = sptr(p);
    asm volatile("ldmatrix.sync.aligned.m8n8.x4.shared.b16 {%0,%1,%2,%3}, [%4];"
                 : "=r"(r[0]), "=r"(r[1]), "=r"(r[2]), "=r"(r[3]) : "r"(a));
}
__device__ __forceinline__ void ldB(unsigned r[2], const float* base, int L) {
    int lane = threadIdx.x & 31;
    const float* p = base + (lane & 7) * L + ((lane & 8) ? 4 : 0);
    unsigned a = sptr(p);
    asm volatile("ldmatrix.sync.aligned.m8n8.x2.shared.b16 {%0,%1}, [%2];"
                 : "=r"(r[0]), "=r"(r[1]) : "r"(a));
}
__device__ __forceinline__ unsigned ldsm(const float* p) { return __float_as_uint(*p); }

__global__ __launch_bounds__(THREADS, 1)
void swin_win_attn_kernel(const float* __restrict__ x,
                          const float* __restrict__ mask,
                          const float* __restrict__ qkv_w,
                          const float* __restrict__ qkv_b,
                          const float* __restrict__ proj_w,
                          const float* __restrict__ proj_b,
                          const float* __restrict__ tbl_g,
                          const int*   __restrict__ idx_g,
                          float* __restrict__ out) {
    extern __shared__ float sm[];
    int*   idx_s = (int*)(sm + IDXO);
    float* msk_s = sm + MSKO;
    float* tbl_s = sm + TBLO;

    const int tid  = threadIdx.x;
    const int lane = tid & 31;
    const int w    = tid >> 5;
    const int b    = blockIdx.x;
    const int win  = b & (NWIN - 1);

    const int wm = w & 3;       // M-tile (16 rows)
    const int wn = w >> 2;      // N-tile in GEMMs / head in attention
    const int ar = lane >> 2;
    const int ac = lane & 3;

    // ---- stage rel index, mask, bias table ----
    for (int i = tid; i < NTOK * NTOK; i += THREADS) idx_s[i] = idx_g[i];
    {
        const float* mg = mask + (size_t)win * NTOK * NTOK;
        for (int i = tid; i < NTOK * NTOK; i += THREADS) msk_s[i] = __ldg(mg + i);
    }
    for (int i = tid; i < 169 * NHD; i += THREADS) tbl_s[i] = tbl_g[i];

    // ---- zero pad rows of x tile, then stage x (tf32) with STS.128 ----
    for (int i = tid; i < (MPAD - NTOK) * DIMC; i += THREADS) {
        int r = NTOK + i / DIMC, c = i % DIMC;
        sm[XS + r * LDX + c] = 0.f;
    }
    {
        const float4* xg = (const float4*)(x + (size_t)b * NTOK * DIMC);
        for (int i = tid; i < NTOK * DIMC / 4; i += THREADS) {
            int r = i >> 5, c4 = i & 31;
            *(float4*)(sm + XS + r * LDX + c4 * 4) = f2tf4(__ldg(xg + i));
        }
    }
    __syncthreads();

    // ================= QKV: 3 chunks of 128 output cols =================
    for (int ch = 0; ch < 3; ++ch) {
        const float4* wg = (const float4*)(qkv_w + ch * DIMC * DIMC);
        for (int i = tid; i < DIMC * DIMC / 4; i += THREADS) {
            int r = i >> 5, c4 = i & 31;
            *(float4*)(sm + WSO + r * LDX + c4 * 4) = f2tf4(__ldg(wg + i));
        }
        __syncthreads();

        float acc[4][4];
        #pragma unroll
        for (int t = 0; t < 4; ++t)
            #pragma unroll
            for (int j = 0; j < 4; ++j) acc[t][j] = 0.f;

        #pragma unroll 4
        for (int k0 = 0; k0 < DIMC; k0 += 8) {
            unsigned a[4];
            ldA(a, sm + XS + (wm * 16) * LDX + k0, LDX);
            #pragma unroll
            for (int t = 0; t < 4; ++t) {
                unsigned bb[2];
                ldB(bb, sm + WSO + (wn * 32 + t * 8) * LDX + k0, LDX);
                mma8(acc[t], a[0], a[1], a[2], a[3], bb[0], bb[1]);
            }
        }

        float* dst = sm + (ch == 0 ? QS : (ch == 1 ? KS : VS));
        float scl = (ch == 0) ? SCALE : 1.f;
        #pragma unroll
        for (int t = 0; t < 4; ++t) {
            int col = wn * 32 + t * 8 + 2 * ac;
            float b0v = __ldg(qkv_b + ch * DIMC + col);
            float b1v = __ldg(qkv_b + ch * DIMC + col + 1);
            int r0 = wm * 16 + ar;
            dst[r0 * LDX + col]           = __uint_as_float(f2tf((acc[t][0] + b0v) * scl));
            dst[r0 * LDX + col + 1]       = __uint_as_float(f2tf((acc[t][1] + b1v) * scl));
            dst[(r0 + 8) * LDX + col]     = __uint_as_float(f2tf((acc[t][2] + b0v) * scl));
            dst[(r0 + 8) * LDX + col + 1] = __uint_as_float(f2tf((acc[t][3] + b1v) * scl));
        }
        __syncthreads();
    }

    // ================= attention: all 4 heads in parallel =================
    const int h = wn;                       // warp's head
    float* sb = sm + SSO + h * SBUF;        // this head's score buffer

    // --- scores S_h = Q_h @ K_h^T (64x64, K=32); warp tile 16x64 ---
    {
        float sacc[8][4];
        #pragma unroll
        for (int t = 0; t < 8; ++t)
            #pragma unroll
            for (int j = 0; j < 4; ++j) sacc[t][j] = 0.f;

        #pragma unroll
        for (int kk = 0; kk < 4; ++kk) {
            int k0 = h * HD + kk * 8;
            unsigned a[4];
            ldA(a, sm + QS + (wm * 16) * LDX + k0, LDX);
            #pragma unroll
            for (int t = 0; t < 8; ++t) {
                unsigned bb[2];
                ldB(bb, sm + KS + (t * 8) * LDX + k0, LDX);
                mma8(sacc[t], a[0], a[1], a[2], a[3], bb[0], bb[1]);
            }
        }
        #pragma unroll
        for (int t = 0; t < 8; ++t) {
            int m0 = t * 8 + 2 * ac;
            int r0 = wm * 16 + ar;
            sb[r0 * LDS2 + m0]           = sacc[t][0];
            sb[r0 * LDS2 + m0 + 1]       = sacc[t][1];
            sb[(r0 + 8) * LDS2 + m0]     = sacc[t][2];
            sb[(r0 + 8) * LDS2 + m0 + 1] = sacc[t][3];
        }
    }
    __syncthreads();

    // --- softmax with rel-bias + shift-mask; warp owns 16 rows of its head ---
    #pragma unroll 4
    for (int rr = 0; rr < 16; ++rr) {
        int n = wm * 16 + rr;
        float s0 = -1e30f, s1 = -1e30f;
        if (n < NTOK) {
            if (lane < NTOK)
                s0 = sb[n * LDS2 + lane]
                   + tbl_s[idx_s[n * NTOK + lane] * NHD + h]
                   + msk_s[n * NTOK + lane];
            int m1 = lane + 32;
            if (m1 < NTOK)
                s1 = sb[n * LDS2 + m1]
                   + tbl_s[idx_s[n * NTOK + m1] * NHD + h]
                   + msk_s[n * NTOK + m1];
        }
        float mx = fmaxf(s0, s1);
        #pragma unroll
        for (int o = 16; o; o >>= 1) mx = fmaxf(mx, __shfl_xor_sync(0xffffffffu, mx, o));
        float e0 = (s0 > -1e29f) ? __expf(s0 - mx) : 0.f;
        float e1 = (s1 > -1e29f) ? __expf(s1 - mx) : 0.f;
        float sum = e0 + e1;
        #pragma unroll
        for (int o = 16; o; o >>= 1) sum += __shfl_xor_sync(0xffffffffu, sum, o);
        if (n < NTOK) {
            float inv = 1.f / sum;
            sb[n * LDS2 + lane]      = __uint_as_float(f2tf(e0 * inv));
            sb[n * LDS2 + lane + 32] = __uint_as_float(f2tf(e1 * inv));
        } else {
            sb[n * LDS2 + lane]      = 0.f;
            sb[n * LDS2 + lane + 32] = 0.f;
        }
    }
    __syncthreads();

    // --- ctx_h = P_h @ V_h (64x32, K=64); warp tile 16x32 ---
    {
        float cacc[4][4];
        #pragma unroll
        for (int u = 0; u < 4; ++u)
            #pragma unroll
            for (int j = 0; j < 4; ++j) cacc[u][j] = 0.f;

        #pragma unroll
        for (int k0 = 0; k0 < MPAD; k0 += 8) {
            unsigned a[4];
            ldA(a, sb + (wm * 16) * LDS2 + k0, LDS2);
            #pragma unroll
            for (int u = 0; u < 4; ++u) {
                int n0 = h * HD + u * 8;
                unsigned b0 = ldsm(sm + VS + (k0 + ac) * LDX + n0 + ar);
                unsigned b1 = ldsm(sm + VS + (k0 + 4 + ac) * LDX + n0 + ar);
                mma8(cacc[u], a[0], a[1], a[2], a[3], b0, b1);
            }
        }
        __syncthreads();   // scores no longer needed; XS rewrite is safe (XS!=SSO)
        #pragma unroll
        for (int u = 0; u < 4; ++u) {
            int col = h * HD + u * 8 + 2 * ac;
            int r0 = wm * 16 + ar;
            sm[XS + r0 * LDX + col]           = __uint_as_float(f2tf(cacc[u][0]));
            sm[XS + r0 * LDX + col + 1]       = __uint_as_float(f2tf(cacc[u][1]));
            sm[XS + (r0 + 8) * LDX + col]     = __uint_as_float(f2tf(cacc[u][2]));
            sm[XS + (r0 + 8) * LDX + col + 1] = __uint_as_float(f2tf(cacc[u][3]));
        }
    }
    __syncthreads();

    // ================= proj: out = ctx @ proj_w^T + proj_b =================
    {
        const float4* pg = (const float4*)proj_w;
        for (int i = tid; i < DIMC * DIMC / 4; i += THREADS) {
            int r = i >> 5, c4 = i & 31;
            *(float4*)(sm + WSO + r * LDX + c4 * 4) = f2tf4(__ldg(pg + i));
        }
        __syncthreads();

        float pacc[4][4];
        #pragma unroll
        for (int t = 0; t < 4; ++t)
            #pragma unroll
            for (int j = 0; j < 4; ++j) pacc[t][j] = 0.f;

        #pragma unroll 4
        for (int k0 = 0; k0 < DIMC; k0 += 8) {
            unsigned a[4];
            ldA(a, sm + XS + (wm * 16) * LDX + k0, LDX);
            #pragma unroll
            for (int t = 0; t < 4; ++t) {
                unsigned bb[2];
                ldB(bb, sm + WSO + (wn * 32 + t * 8) * LDX + k0, LDX);
                mma8(pacc[t], a[0], a[1], a[2], a[3], bb[0], bb[1]);
            }
        }

        float* og = out + (size_t)b * NTOK * DIMC;
        #pragma unroll
        for (int t = 0; t < 4; ++t) {
            int col = wn * 32 + t * 8 + 2 * ac;
            float b0v = __ldg(proj_b + col);
            float b1v = __ldg(proj_b + col + 1);
            int r0 = wm * 16 + ar;
            if (r0 < NTOK) {
                og[r0 * DIMC + col]     = pacc[t][0] + b0v;
                og[r0 * DIMC + col + 1] = pacc[t][1] + b1v;
            }
            if (r0 + 8 < NTOK) {
                og[(r0 + 8) * DIMC + col]     = pacc[t][2] + b0v;
                og[(r0 + 8) * DIMC + col + 1] = pacc[t][3] + b1v;
            }
        }
    }
}

extern "C" void kernel_launch(void* const* d_in, const int* in_sizes, int n_in,
                              void* d_out, int out_size) {
    const float* x      = (const float*)d_in[0];
    const float* mask   = (const float*)d_in[1];
    const float* qkv_w  = (const float*)d_in[2];
    const float* qkv_b  = (const float*)d_in[3];
    const float* proj_w = (const float*)d_in[4];
    const float* proj_b = (const float*)d_in[5];
    const float* tbl    = (const float*)d_in[6];
    const int*   idx    = (const int*)d_in[7];

    cudaFuncSetAttribute(swin_win_attn_kernel,
                         cudaFuncAttributeMaxDynamicSharedMemorySize,
                         SMEM_FLOATS * 4);

    swin_win_attn_kernel<<<4096, THREADS, SMEM_FLOATS * 4>>>(
        x, mask, qkv_w, qkv_b, proj_w, proj_b, tbl, idx, (float*)d_out);
}